// round 7
// baseline (speedup 1.0000x reference)
#include <cuda_runtime.h>
#include <math_constants.h>

#define B       4
#define M       76800          // 240*320 targets per batch
#define NC      256
#define NCHUNK  75             // blocks per batch (1024 targets each)
#define NBLK    (NCHUNK * B)   // 300

__device__ unsigned g_maxkey;          // monotonic masked-max key (idempotent across replays)
__device__ int      g_anyinv;          // any masked-out pixel (idempotent)
__device__ float    g_csort[B * NC];   // sorted centers (written by blockIdx.x==0 blocks)
__device__ unsigned g_ckey[B * NC];    // per-slot min dist, INVERTED key; 0 == +inf (reset by finalizer)
__device__ float    g_d2part[NBLK];
__device__ unsigned g_cnt;             // last-block ticket (reset by finalizer)

__device__ __forceinline__ unsigned fkey(float f) {
    unsigned b = __float_as_uint(f);
    return b ^ ((b & 0x80000000u) ? 0xFFFFFFFFu : 0x80000000u);
}
__device__ __forceinline__ float funkey(unsigned k) {
    return __uint_as_float(k ^ ((k & 0x80000000u) ? 0x80000000u : 0xFFFFFFFFu));
}

// ---------------------------------------------------------------------------
// Single fused kernel. grid = (NCHUNK, B), block = 256.
//  per block: local rank-sort of centers -> binary-search bracket pass over
//  its 1024 targets -> global merges. Last block (ticket) finalizes:
//  distance transform + pad terms + total sum -> out[0].
// ---------------------------------------------------------------------------
__global__ void __launch_bounds__(256) k_fused(const float4* __restrict__ t4,
                                               const int4*   __restrict__ m4,
                                               const float*  __restrict__ centers,
                                               float*        __restrict__ out) {
    __shared__ __align__(16) float scraw[NC];
    __shared__ float    scs[NC];        // sorted centers
    __shared__ unsigned scmin[NC];
    __shared__ float    ssum[8], smax[8];
    __shared__ float    A[NC], Bv[NC];  // finalize scratch
    __shared__ bool     is_last;

    const int tid = threadIdx.x;
    const int b   = blockIdx.y;

    // ---- local rank-sort of this batch's centers (exact, index tie-break) ----
    scraw[tid] = centers[b * NC + tid];
    scmin[tid] = 0x7F800000u;            // +inf
    __syncthreads();
    {
        const float v0 = scraw[tid];
        int rank = 0;
        const float4* sr4 = (const float4*)scraw;
        #pragma unroll 8
        for (int j4 = 0; j4 < NC / 4; j4++) {
            float4 c = sr4[j4];
            int j = 4 * j4;
            rank += (c.x < v0 || (c.x == v0 && j + 0 < tid)) ? 1 : 0;
            rank += (c.y < v0 || (c.y == v0 && j + 1 < tid)) ? 1 : 0;
            rank += (c.z < v0 || (c.z == v0 && j + 2 < tid)) ? 1 : 0;
            rank += (c.w < v0 || (c.w == v0 && j + 3 < tid)) ? 1 : 0;
        }
        scs[rank] = v0;
    }
    __syncthreads();
    if (blockIdx.x == 0) g_csort[b * NC + tid] = scs[tid];  // for finalizer

    // ---- main pass: one float4/int4 per thread ----
    const int gi = b * (M / 4) + blockIdx.x * 256 + tid;
    float4 tv = t4[gi];
    int4   mv = m4[gi];
    float tval[4] = {tv.x, tv.y, tv.z, tv.w};
    int   mok[4]  = {mv.x, mv.y, mv.z, mv.w};

    float s = 0.0f;
    float mloc = -CUDART_INF_F;
    int inv = 0;
    #pragma unroll
    for (int q = 0; q < 4; q++) {
        float tk = tval[q];
        if (mok[q]) {
            mloc = fmaxf(mloc, tk);
            int cnt = 0;                       // # sorted centers <= tk
            #pragma unroll
            for (int st = 128; st; st >>= 1)
                if (scs[cnt + st - 1] <= tk) cnt += st;
            float dlo = (cnt >= 1) ? tk - scs[cnt - 1] : CUDART_INF_F;
            float dhi = (cnt < NC) ? scs[cnt] - tk     : CUDART_INF_F;
            float d = fminf(dlo, dhi);
            s += d * d;
            if (cnt >= 1) atomicMin(&scmin[cnt - 1], __float_as_uint(dlo));
            if (cnt < NC) atomicMin(&scmin[cnt],     __float_as_uint(dhi));
        } else {
            inv = 1;
        }
    }

    #pragma unroll
    for (int o = 16; o; o >>= 1) {
        s   += __shfl_xor_sync(0xFFFFFFFFu, s, o);
        mloc = fmaxf(mloc, __shfl_xor_sync(0xFFFFFFFFu, mloc, o));
    }
    if ((tid & 31) == 0) { ssum[tid >> 5] = s; smax[tid >> 5] = mloc; }
    int banyinv = __syncthreads_or(inv);

    // merge per-block center mins (inverted key; global init/reset value 0 == +inf)
    unsigned sm = scmin[tid];
    if (sm != 0x7F800000u) atomicMax(&g_ckey[b * NC + tid], ~sm);

    if (tid == 0) {
        float bs = ssum[0], bm = smax[0];
        #pragma unroll
        for (int j = 1; j < 8; j++) { bs += ssum[j]; bm = fmaxf(bm, smax[j]); }
        g_d2part[b * NCHUNK + blockIdx.x] = bs;
        atomicMax(&g_maxkey, fkey(bm));
        if (banyinv) g_anyinv = 1;           // benign same-value race
    }

    // ---- last-block ticket ----
    __threadfence();
    if (tid == 0) is_last = (atomicAdd(&g_cnt, 1u) == NBLK - 1);
    __syncthreads();
    if (!is_last) return;
    __threadfence();

    // =========================== FINALIZE (1 block) ===========================
    const float mt = funkey(g_maxkey);
    const float mc = fmaxf(fmaxf(g_csort[NC - 1],          g_csort[NC + NC - 1]),
                           fmaxf(g_csort[2 * NC + NC - 1], g_csort[3 * NC + NC - 1]));
    const float mx = fmaxf(mt, mc), mn = fminf(mt, mc);
    const float pad = mx + (mx - mn) + 1.0f;   // EPS = 1.0
    const int anyinv = g_anyinv;

    float acc = 0.0f;
    for (int bb = 0; bb < B; bb++) {
        float c = g_csort[bb * NC + tid];
        unsigned key = g_ckey[bb * NC + tid];
        g_ckey[bb * NC + tid] = 0u;            // reset for next replay
        float d = key ? __uint_as_float(~key) : CUDART_INF_F;
        A[tid]        = d - c;
        Bv[255 - tid] = d + c;                 // reversed: prefix-min == suffix-min
        __syncthreads();
        #pragma unroll
        for (int off = 1; off < NC; off <<= 1) {
            float a  = A[tid],  ap = (tid >= off) ? A[tid - off]  : CUDART_INF_F;
            float b2 = Bv[tid], bp = (tid >= off) ? Bv[tid - off] : CUDART_INF_F;
            __syncthreads();
            A[tid]  = fminf(a, ap);
            Bv[tid] = fminf(b2, bp);
            __syncthreads();
        }
        float Di = fminf(A[tid] + c, Bv[255 - tid] - c);
        if (anyinv) Di = fminf(Di, pad - c);
        acc += Di * Di;
        __syncthreads();                       // protect A/Bv before next batch
    }
    if (tid == 0) {
        if (!anyinv) { float dp = pad - mt; acc += dp * dp; }  // pad-center row
        g_cnt = 0u;                            // reset ticket for next replay
    }
    for (int i = tid; i < NBLK; i += 256) acc += g_d2part[i];

    #pragma unroll
    for (int o = 16; o; o >>= 1) acc += __shfl_xor_sync(0xFFFFFFFFu, acc, o);
    if ((tid & 31) == 0) ssum[tid >> 5] = acc;
    __syncthreads();
    if (tid == 0) {
        float tot = ssum[0];
        #pragma unroll
        for (int j = 1; j < 8; j++) tot += ssum[j];
        out[0] = tot * 0.25f;
    }
}

// ---------------------------------------------------------------------------
extern "C" void kernel_launch(void* const* d_in, const int* in_sizes, int n_in,
                              void* d_out, int out_size) {
    const float4* t4      = (const float4*)d_in[0];
    const float*  centers = (const float*)d_in[1];
    const int4*   m4      = (const int4*)d_in[2];
    float*        out     = (float*)d_out;

    dim3 grid(NCHUNK, B);
    k_fused<<<grid, 256>>>(t4, m4, centers, out);
}

// round 8
// speedup vs baseline: 1.0019x; 1.0019x over previous
#include <cuda_runtime.h>
#include <math_constants.h>

#define B       4
#define M       76800          // 240*320 targets per batch
#define NC      256
#define NBLK    300            // 75 chunks x 4 batches; chunk = bid>>2, b = bid&3

__device__ unsigned g_maxkey;          // monotonic masked-max key (idempotent across replays)
__device__ int      g_anyinv;          // any masked-out pixel (idempotent)
__device__ float    g_csort[B * NC];   // sorted centers (published by blocks 0..3)
__device__ unsigned g_flag[B];         // per-batch "sorted ready" flag (reset by finalizer)
__device__ unsigned g_ckey[B * NC];    // per-slot min dist, INVERTED key; 0 == +inf (reset by finalizer)
__device__ float    g_d2part[NBLK];
__device__ unsigned g_cnt;             // last-block ticket (reset by finalizer)

__device__ __forceinline__ unsigned fkey(float f) {
    unsigned b = __float_as_uint(f);
    return b ^ ((b & 0x80000000u) ? 0xFFFFFFFFu : 0x80000000u);
}
__device__ __forceinline__ float funkey(unsigned k) {
    return __uint_as_float(k ^ ((k & 0x80000000u) ? 0x80000000u : 0xFFFFFFFFu));
}

// inclusive prefix-min over 256 threads (2 barriers)
__device__ __forceinline__ float blk_min_scan(float v, int tid, float* wa) {
    #pragma unroll
    for (int o = 1; o < 32; o <<= 1) {
        float u = __shfl_up_sync(0xFFFFFFFFu, v, o);
        if ((tid & 31) >= o) v = fminf(v, u);
    }
    if ((tid & 31) == 31) wa[tid >> 5] = v;
    __syncthreads();
    float pre = CUDART_INF_F;
    const int w = tid >> 5;
    #pragma unroll
    for (int j = 0; j < 7; j++)
        if (j < w) pre = fminf(pre, wa[j]);
    __syncthreads();
    return fminf(v, pre);
}
// inclusive suffix-min over 256 threads (2 barriers)
__device__ __forceinline__ float blk_min_scan_rev(float v, int tid, float* wa) {
    #pragma unroll
    for (int o = 1; o < 32; o <<= 1) {
        float u = __shfl_down_sync(0xFFFFFFFFu, v, o);
        if ((tid & 31) + o < 32) v = fminf(v, u);
    }
    if ((tid & 31) == 0) wa[tid >> 5] = v;
    __syncthreads();
    float pre = CUDART_INF_F;
    const int w = tid >> 5;
    #pragma unroll
    for (int j = 1; j < 8; j++)
        if (j > w) pre = fminf(pre, wa[j]);
    __syncthreads();
    return fminf(v, pre);
}

__global__ void __launch_bounds__(256) k_fused(const float4* __restrict__ t4,
                                               const int4*   __restrict__ m4,
                                               const float*  __restrict__ centers,
                                               float*        __restrict__ out) {
    __shared__ __align__(16) float scraw[NC];
    __shared__ float    scs[NC];
    __shared__ unsigned scmin[NC];
    __shared__ float    ssum[8], smax[8], wa[8];
    __shared__ bool     is_last;

    const int tid   = threadIdx.x;
    const int bid   = blockIdx.x;
    const int b     = bid & 3;
    const int chunk = bid >> 2;     // 0..74

    scmin[tid] = 0x7F800000u;       // +inf

    // ---- prefetch this block's targets & mask; local max / any-invalid ----
    const int gi = b * (M / 4) + chunk * 256 + tid;
    float4 tv = t4[gi];
    int4   mv = m4[gi];
    float tval[4] = {tv.x, tv.y, tv.z, tv.w};
    int   mok[4]  = {mv.x, mv.y, mv.z, mv.w};
    float mloc = -CUDART_INF_F;
    int inv = 0;
    #pragma unroll
    for (int q = 0; q < 4; q++) {
        if (mok[q]) mloc = fmaxf(mloc, tval[q]); else inv = 1;
    }

    // ---- sorted centers: blocks 0..3 produce; others consume via flag ----
    if (chunk == 0) {
        scraw[tid] = centers[b * NC + tid];
        __syncthreads();
        const float v0 = scraw[tid];
        int rank = 0;
        const float4* sr4 = (const float4*)scraw;
        #pragma unroll 8
        for (int j4 = 0; j4 < NC / 4; j4++) {
            float4 c = sr4[j4];
            int j = 4 * j4;
            rank += (c.x < v0 || (c.x == v0 && j + 0 < tid)) ? 1 : 0;
            rank += (c.y < v0 || (c.y == v0 && j + 1 < tid)) ? 1 : 0;
            rank += (c.z < v0 || (c.z == v0 && j + 2 < tid)) ? 1 : 0;
            rank += (c.w < v0 || (c.w == v0 && j + 3 < tid)) ? 1 : 0;
        }
        scs[rank] = v0;
        __syncthreads();
        g_csort[b * NC + tid] = scs[tid];
        __threadfence();
        __syncthreads();
        if (tid == 0) atomicExch(&g_flag[b], 1u);
    } else {
        if (tid == 0) {
            while (atomicAdd(&g_flag[b], 0u) == 0u) __nanosleep(64);
            __threadfence();
        }
        __syncthreads();
        scs[tid] = __ldcg(&g_csort[b * NC + tid]);
        __syncthreads();
    }

    // ---- main pass: bracket search + smem atomicMin + dist2 sum ----
    float s = 0.0f;
    #pragma unroll
    for (int q = 0; q < 4; q++) {
        if (mok[q]) {
            float tk = tval[q];
            int cnt = 0;                       // # sorted centers <= tk
            #pragma unroll
            for (int st = 128; st; st >>= 1)
                if (scs[cnt + st - 1] <= tk) cnt += st;
            float dlo = (cnt >= 1) ? tk - scs[cnt - 1] : CUDART_INF_F;
            float dhi = (cnt < NC) ? scs[cnt] - tk     : CUDART_INF_F;
            float d = fminf(dlo, dhi);
            s += d * d;
            if (cnt >= 1) atomicMin(&scmin[cnt - 1], __float_as_uint(dlo));
            if (cnt < NC) atomicMin(&scmin[cnt],     __float_as_uint(dhi));
        }
    }

    #pragma unroll
    for (int o = 16; o; o >>= 1) {
        s   += __shfl_xor_sync(0xFFFFFFFFu, s, o);
        mloc = fmaxf(mloc, __shfl_xor_sync(0xFFFFFFFFu, mloc, o));
    }
    if ((tid & 31) == 0) { ssum[tid >> 5] = s; smax[tid >> 5] = mloc; }
    int banyinv = __syncthreads_or(inv);

    // merge per-block center mins (inverted key; 0 == +inf)
    unsigned sm = scmin[tid];
    if (sm != 0x7F800000u) atomicMax(&g_ckey[b * NC + tid], ~sm);

    if (tid == 0) {
        float bs = ssum[0], bm = smax[0];
        #pragma unroll
        for (int j = 1; j < 8; j++) { bs += ssum[j]; bm = fmaxf(bm, smax[j]); }
        g_d2part[bid] = bs;
        atomicMax(&g_maxkey, fkey(bm));
        if (banyinv) g_anyinv = 1;           // benign same-value race
    }

    // ---- last-block ticket ----
    __threadfence();
    if (tid == 0) is_last = (atomicAdd(&g_cnt, 1u) == NBLK - 1);
    __syncthreads();
    if (!is_last) return;
    __threadfence();

    // =========================== FINALIZE (1 block) ===========================
    const float mt = funkey(g_maxkey);
    const float mc = fmaxf(fmaxf(__ldcg(&g_csort[NC - 1]),          __ldcg(&g_csort[NC + NC - 1])),
                           fmaxf(__ldcg(&g_csort[2 * NC + NC - 1]), __ldcg(&g_csort[3 * NC + NC - 1])));
    const float mx = fmaxf(mt, mc), mn = fminf(mt, mc);
    const float pad = mx + (mx - mn) + 1.0f;   // EPS = 1.0
    const int anyinv = g_anyinv;

    float acc = 0.0f;
    #pragma unroll
    for (int bb = 0; bb < B; bb++) {
        float c = __ldcg(&g_csort[bb * NC + tid]);
        unsigned key = __ldcg(&g_ckey[bb * NC + tid]);
        g_ckey[bb * NC + tid] = 0u;            // reset for next replay
        float d = key ? __uint_as_float(~key) : CUDART_INF_F;
        float As = blk_min_scan(d - c, tid, wa);        // prefix-min of d_j - c_j
        float Bs = blk_min_scan_rev(d + c, tid, wa);    // suffix-min of d_j + c_j
        float Di = fminf(As + c, Bs - c);
        if (anyinv) Di = fminf(Di, pad - c);
        acc += Di * Di;
    }
    if (tid == 0) {
        if (!anyinv) { float dp = pad - mt; acc += dp * dp; }  // pad-center row
        g_cnt = 0u;
        g_flag[0] = 0u; g_flag[1] = 0u; g_flag[2] = 0u; g_flag[3] = 0u;
    }
    for (int i = tid; i < NBLK; i += 256) acc += g_d2part[i];

    #pragma unroll
    for (int o = 16; o; o >>= 1) acc += __shfl_xor_sync(0xFFFFFFFFu, acc, o);
    if ((tid & 31) == 0) ssum[tid >> 5] = acc;
    __syncthreads();
    if (tid == 0) {
        float tot = ssum[0];
        #pragma unroll
        for (int j = 1; j < 8; j++) tot += ssum[j];
        out[0] = tot * 0.25f;
    }
}

// ---------------------------------------------------------------------------
extern "C" void kernel_launch(void* const* d_in, const int* in_sizes, int n_in,
                              void* d_out, int out_size) {
    const float4* t4      = (const float4*)d_in[0];
    const float*  centers = (const float*)d_in[1];
    const int4*   m4      = (const int4*)d_in[2];
    float*        out     = (float*)d_out;

    k_fused<<<NBLK, 256>>>(t4, m4, centers, out);
}

// round 9
// speedup vs baseline: 1.1186x; 1.1165x over previous
#include <cuda_runtime.h>
#include <math_constants.h>

#define B       4
#define M       76800          // 240*320 targets per batch
#define NC      256
#define NCON    300            // consumer blocks: chunk = bid-4; b = chunk&3, sub = chunk>>2
#define NBLK    304            // 4 sorter blocks + 300 consumers

__device__ unsigned g_maxkey;          // monotonic masked-max key (idempotent across replays)
__device__ int      g_anyinv;          // any masked-out pixel (idempotent)
__device__ float    g_csort[B * NC];   // sorted centers
__device__ int      g_lut[B * 257];    // exclusive bucket-start LUT (lut[256] = 256)
__device__ float    g_meta[B * 2];     // {lo, scale} per batch
__device__ unsigned g_flag[B];         // per-batch ready flag (reset by finalizer)
__device__ unsigned g_ckey[B * NC];    // min dist per slot, INVERTED key; 0 == +inf (reset by finalizer)
__device__ float    g_d2part[NCON];
__device__ unsigned g_cnt;             // ticket (reset by finalizer)

__device__ __forceinline__ unsigned fkey(float f) {
    unsigned b = __float_as_uint(f);
    return b ^ ((b & 0x80000000u) ? 0xFFFFFFFFu : 0x80000000u);
}
__device__ __forceinline__ float funkey(unsigned k) {
    return __uint_as_float(k ^ ((k & 0x80000000u) ? 0x80000000u : 0xFFFFFFFFu));
}

// inclusive prefix-min over 256 threads (2 barriers)
__device__ __forceinline__ float blk_min_scan(float v, int tid, float* wa) {
    #pragma unroll
    for (int o = 1; o < 32; o <<= 1) {
        float u = __shfl_up_sync(0xFFFFFFFFu, v, o);
        if ((tid & 31) >= o) v = fminf(v, u);
    }
    if ((tid & 31) == 31) wa[tid >> 5] = v;
    __syncthreads();
    float pre = CUDART_INF_F;
    const int w = tid >> 5;
    #pragma unroll
    for (int j = 0; j < 7; j++)
        if (j < w) pre = fminf(pre, wa[j]);
    __syncthreads();
    return fminf(v, pre);
}
// inclusive suffix-min over 256 threads (2 barriers)
__device__ __forceinline__ float blk_min_scan_rev(float v, int tid, float* wa) {
    #pragma unroll
    for (int o = 1; o < 32; o <<= 1) {
        float u = __shfl_down_sync(0xFFFFFFFFu, v, o);
        if ((tid & 31) + o < 32) v = fminf(v, u);
    }
    if ((tid & 31) == 0) wa[tid >> 5] = v;
    __syncthreads();
    float pre = CUDART_INF_F;
    const int w = tid >> 5;
    #pragma unroll
    for (int j = 1; j < 8; j++)
        if (j > w) pre = fminf(pre, wa[j]);
    __syncthreads();
    return fminf(v, pre);
}

__global__ void __launch_bounds__(256) k_fused(const float4* __restrict__ t4,
                                               const int4*   __restrict__ m4,
                                               const float*  __restrict__ centers,
                                               float*        __restrict__ out) {
    __shared__ __align__(16) float scs[NC];
    __shared__ int      slut[257];
    __shared__ unsigned scmin[NC];
    __shared__ __align__(16) float scraw[NC];
    __shared__ int      shist[NC];
    __shared__ int      swa[8];
    __shared__ float    sred[8], sred2[8], wa[8];
    __shared__ float    smeta[2];
    __shared__ bool     is_last;

    const int tid = threadIdx.x;
    const int bid = blockIdx.x;

    if (bid < B) {
        // ======================= SORTER BLOCK (batch = bid) =======================
        const int b = bid;
        scraw[tid] = centers[b * NC + tid];
        __syncthreads();
        const float v0 = scraw[tid];
        int rank = 0;
        const float4* sr4 = (const float4*)scraw;
        #pragma unroll 8
        for (int j4 = 0; j4 < NC / 4; j4++) {
            float4 c = sr4[j4];
            int j = 4 * j4;
            rank += (c.x < v0 || (c.x == v0 && j + 0 < tid)) ? 1 : 0;
            rank += (c.y < v0 || (c.y == v0 && j + 1 < tid)) ? 1 : 0;
            rank += (c.z < v0 || (c.z == v0 && j + 2 < tid)) ? 1 : 0;
            rank += (c.w < v0 || (c.w == v0 && j + 3 < tid)) ? 1 : 0;
        }
        scs[rank] = v0;
        shist[tid] = 0;
        __syncthreads();

        const float lo = scs[0], hi = scs[255];
        const float scale = (hi > lo) ? 256.0f / (hi - lo) : 0.0f;
        int q = (int)((scs[tid] - lo) * scale);
        q = min(255, max(q, 0));
        atomicAdd(&shist[q], 1);
        __syncthreads();

        // exclusive prefix sum of shist -> bucket starts
        int h = shist[tid];
        int incl = h;
        #pragma unroll
        for (int o = 1; o < 32; o <<= 1) {
            int u = __shfl_up_sync(0xFFFFFFFFu, incl, o);
            if ((tid & 31) >= o) incl += u;
        }
        if ((tid & 31) == 31) swa[tid >> 5] = incl;
        __syncthreads();
        int add = 0;
        #pragma unroll
        for (int j = 0; j < 8; j++)
            if (j < (tid >> 5)) add += swa[j];
        g_lut[b * 257 + tid]  = add + incl - h;
        g_csort[b * NC + tid] = scs[tid];
        if (tid == 0) {
            g_lut[b * 257 + 256] = NC;
            g_meta[2 * b]     = lo;
            g_meta[2 * b + 1] = scale;
        }
        __threadfence();
        __syncthreads();
        if (tid == 0) atomicExch(&g_flag[b], 1u);
    } else {
        // ========================= CONSUMER BLOCK =========================
        const int chunk = bid - B;
        const int b   = chunk & 3;
        const int sub = chunk >> 2;

        scmin[tid] = 0x7F800000u;   // +inf

        // prefetch targets/mask; masked max + any-invalid (overlaps sorter)
        const int gi = b * (M / 4) + sub * 256 + tid;
        float4 tv = t4[gi];
        int4   mv = m4[gi];
        float tval[4] = {tv.x, tv.y, tv.z, tv.w};
        int   mok[4]  = {mv.x, mv.y, mv.z, mv.w};
        float mloc = -CUDART_INF_F;
        int inv = 0;
        #pragma unroll
        for (int qq = 0; qq < 4; qq++) {
            if (mok[qq]) mloc = fmaxf(mloc, tval[qq]); else inv = 1;
        }

        // wait for this batch's sorted centers + LUT
        if (tid == 0) {
            while (__ldcg(&g_flag[b]) == 0u) __nanosleep(128);
            __threadfence();
        }
        __syncthreads();
        scs[tid]  = __ldcg(&g_csort[b * NC + tid]);
        slut[tid] = __ldcg(&g_lut[b * 257 + tid]);
        if (tid == 0) {
            slut[256] = NC;
            smeta[0] = __ldcg(&g_meta[2 * b]);
            smeta[1] = __ldcg(&g_meta[2 * b + 1]);
        }
        __syncthreads();

        const float lo = smeta[0], scale = smeta[1];
        float s = 0.0f;
        #pragma unroll
        for (int qq = 0; qq < 4; qq++) {
            if (mok[qq]) {
                float tk = tval[qq];
                int q = (int)((tk - lo) * scale);
                q = min(255, max(q, 0));
                int j = slut[q], e = slut[q + 1];
                while (j < e && scs[j] <= tk) j++;   // exact lower-bound count (bucket fn monotone)
                float dlo = (j >= 1) ? tk - scs[j - 1] : CUDART_INF_F;
                float dhi = (j < NC) ? scs[j] - tk    : CUDART_INF_F;
                float d = fminf(dlo, dhi);
                s += d * d;
                if (j >= 1) atomicMin(&scmin[j - 1], __float_as_uint(dlo));
                if (j < NC) atomicMin(&scmin[j],     __float_as_uint(dhi));
            }
        }

        #pragma unroll
        for (int o = 16; o; o >>= 1) {
            s   += __shfl_xor_sync(0xFFFFFFFFu, s, o);
            mloc = fmaxf(mloc, __shfl_xor_sync(0xFFFFFFFFu, mloc, o));
        }
        if ((tid & 31) == 0) { sred[tid >> 5] = s; sred2[tid >> 5] = mloc; }
        int banyinv = __syncthreads_or(inv);

        unsigned sm = scmin[tid];
        if (sm != 0x7F800000u) atomicMax(&g_ckey[b * NC + tid], ~sm);

        if (tid == 0) {
            float bs = sred[0], bm = sred2[0];
            #pragma unroll
            for (int j = 1; j < 8; j++) { bs += sred[j]; bm = fmaxf(bm, sred2[j]); }
            g_d2part[chunk] = bs;
            atomicMax(&g_maxkey, fkey(bm));
            if (banyinv) g_anyinv = 1;   // benign same-value race
        }
    }

    // ---------------------------- ticket ----------------------------
    __threadfence();
    if (tid == 0) is_last = (atomicAdd(&g_cnt, 1u) == NBLK - 1);
    __syncthreads();
    if (!is_last) return;
    __threadfence();

    // =========================== FINALIZE (1 block) ===========================
    // prefetch all batches (MLP), then process
    float    cB[B];
    unsigned kB[B];
    #pragma unroll
    for (int bb = 0; bb < B; bb++) {
        cB[bb] = __ldcg(&g_csort[bb * NC + tid]);
        kB[bb] = __ldcg(&g_ckey[bb * NC + tid]);
    }
    const float mt = funkey(g_maxkey);
    const float mc = fmaxf(fmaxf(__ldcg(&g_csort[NC - 1]),          __ldcg(&g_csort[NC + NC - 1])),
                           fmaxf(__ldcg(&g_csort[2 * NC + NC - 1]), __ldcg(&g_csort[3 * NC + NC - 1])));
    const float mx = fmaxf(mt, mc), mn = fminf(mt, mc);
    const float pad = mx + (mx - mn) + 1.0f;   // EPS = 1.0
    const int anyinv = g_anyinv;

    float acc = 0.0f;
    #pragma unroll
    for (int bb = 0; bb < B; bb++) {
        g_ckey[bb * NC + tid] = 0u;            // reset for next replay
        float c = cB[bb];
        float d = kB[bb] ? __uint_as_float(~kB[bb]) : CUDART_INF_F;
        float As = blk_min_scan(d - c, tid, wa);        // prefix-min of d_j - c_j
        float Bs = blk_min_scan_rev(d + c, tid, wa);    // suffix-min of d_j + c_j
        float Di = fminf(As + c, Bs - c);
        if (anyinv) Di = fminf(Di, pad - c);
        acc += Di * Di;
    }
    if (tid == 0) {
        if (!anyinv) { float dp = pad - mt; acc += dp * dp; }  // pad-center row
        g_cnt = 0u;
        g_flag[0] = 0u; g_flag[1] = 0u; g_flag[2] = 0u; g_flag[3] = 0u;
    }
    for (int i = tid; i < NCON; i += 256) acc += g_d2part[i];

    #pragma unroll
    for (int o = 16; o; o >>= 1) acc += __shfl_xor_sync(0xFFFFFFFFu, acc, o);
    if ((tid & 31) == 0) sred[tid >> 5] = acc;
    __syncthreads();
    if (tid == 0) {
        float tot = sred[0];
        #pragma unroll
        for (int j = 1; j < 8; j++) tot += sred[j];
        out[0] = tot * 0.25f;
    }
}

// ---------------------------------------------------------------------------
extern "C" void kernel_launch(void* const* d_in, const int* in_sizes, int n_in,
                              void* d_out, int out_size) {
    const float4* t4      = (const float4*)d_in[0];
    const float*  centers = (const float*)d_in[1];
    const int4*   m4      = (const int4*)d_in[2];
    float*        out     = (float*)d_out;

    k_fused<<<NBLK, 256>>>(t4, m4, centers, out);
}

// round 10
// speedup vs baseline: 1.1210x; 1.0021x over previous
#include <cuda_runtime.h>
#include <math_constants.h>

#define B       4
#define M       76800          // 240*320 targets per batch
#define NC      256
#define NCON    300            // consumer blocks: chunk = bid-4; b = chunk&3, sub = chunk>>2
#define NBLK    304            // 4 sorter blocks + 300 consumers (2/SM on 152 SMs, 1 wave)

__device__ unsigned g_maxkey;          // monotonic masked-max key (idempotent across replays)
__device__ int      g_anyinv;          // any masked-out pixel (idempotent)
__device__ float    g_csort[B * NC];   // sorted centers
__device__ int      g_lut[B * 257];    // exclusive bucket-start LUT
__device__ float    g_meta[B * 2];     // {lo, scale} per batch
__device__ unsigned g_flag[B];         // per-batch ready flag (reset by finalizer)
__device__ unsigned g_ckey[B * NC];    // min dist per slot, INVERTED key; 0 == +inf (reset by finalizer)
__device__ float    g_d2part[NCON];
__device__ unsigned g_cnt;             // ticket (reset by finalizer)

__device__ __forceinline__ unsigned fkey(float f) {
    unsigned b = __float_as_uint(f);
    return b ^ ((b & 0x80000000u) ? 0xFFFFFFFFu : 0x80000000u);
}
__device__ __forceinline__ float funkey(unsigned k) {
    return __uint_as_float(k ^ ((k & 0x80000000u) ? 0x80000000u : 0xFFFFFFFFu));
}

__global__ void __launch_bounds__(1024, 2) k_fused(const float* __restrict__ target,
                                                   const int*   __restrict__ mask,
                                                   const float* __restrict__ centers,
                                                   float*       __restrict__ out) {
    __shared__ __align__(16) float scraw[NC];
    __shared__ float    scs[NC];
    __shared__ int      srank[NC];
    __shared__ int      shist[NC];
    __shared__ int      slut[257];
    __shared__ unsigned scmin[NC];
    __shared__ int      swa[8];
    __shared__ float    wa[32];
    __shared__ float    sred[32], sred2[32];
    __shared__ float    smeta[2];
    __shared__ bool     is_last;

    const int tid  = threadIdx.x;     // 0..1023
    const int bid  = blockIdx.x;
    const int lane = tid & 31;
    const int wid  = tid >> 5;        // 0..31

    if (bid < B) {
        // ======================= SORTER BLOCK (batch = bid) =======================
        const int b = bid;
        if (tid < NC) { scraw[tid] = centers[b * NC + tid]; srank[tid] = 0; shist[tid] = 0; }
        __syncthreads();

        // 4-way-split rank sort: v = tid&255, qc = tid>>8 handles 64 comparisons
        const int v = tid & 255, qc = tid >> 8;
        const float v0 = scraw[v];
        int rank = 0;
        const float4* sr4 = (const float4*)scraw;
        #pragma unroll 16
        for (int j4 = qc * 16; j4 < qc * 16 + 16; j4++) {
            float4 c = sr4[j4];
            int j = 4 * j4;
            rank += (c.x < v0 || (c.x == v0 && j + 0 < v)) ? 1 : 0;
            rank += (c.y < v0 || (c.y == v0 && j + 1 < v)) ? 1 : 0;
            rank += (c.z < v0 || (c.z == v0 && j + 2 < v)) ? 1 : 0;
            rank += (c.w < v0 || (c.w == v0 && j + 3 < v)) ? 1 : 0;
        }
        atomicAdd(&srank[v], rank);
        __syncthreads();
        if (qc == 0) scs[srank[v]] = v0;
        __syncthreads();

        // bucket LUT over [lo, hi]
        const float lo = scs[0], hi = scs[255];
        const float scale = (hi > lo) ? 256.0f / (hi - lo) : 0.0f;
        if (tid < NC) {
            int q = (int)((scs[tid] - lo) * scale);
            q = min(255, max(q, 0));
            atomicAdd(&shist[q], 1);
        }
        __syncthreads();
        int h = 0, incl = 0;
        if (tid < NC) {
            h = shist[tid]; incl = h;
            #pragma unroll
            for (int o = 1; o < 32; o <<= 1) {
                int u = __shfl_up_sync(0xFFFFFFFFu, incl, o);
                if (lane >= o) incl += u;
            }
            if (lane == 31) swa[wid] = incl;
        }
        __syncthreads();
        if (tid < NC) {
            int add = 0;
            #pragma unroll
            for (int j = 0; j < 8; j++)
                if (j < wid) add += swa[j];
            g_lut[b * 257 + tid]  = add + incl - h;
            g_csort[b * NC + tid] = scs[tid];
        }
        if (tid == 0) {
            g_lut[b * 257 + 256] = NC;
            g_meta[2 * b] = lo; g_meta[2 * b + 1] = scale;
        }
        __threadfence();
        __syncthreads();
        if (tid == 0) atomicExch(&g_flag[b], 1u);
    } else {
        // ========================= CONSUMER BLOCK (1 target/thread) =========================
        const int chunk = bid - B;
        const int b   = chunk & 3;
        const int sub = chunk >> 2;

        if (tid < NC) scmin[tid] = 0x7F800000u;   // +inf

        // prefetch (overlaps sorter)
        const int gi = b * M + sub * 1024 + tid;
        const float tk = target[gi];
        const int   ok = mask[gi];
        float mloc = ok ? tk : -CUDART_INF_F;
        int inv = !ok;

        if (tid == 0) {
            while (__ldcg(&g_flag[b]) == 0u) __nanosleep(128);
            __threadfence();
        }
        __syncthreads();
        if (tid < NC) {
            scs[tid]  = __ldcg(&g_csort[b * NC + tid]);
            slut[tid] = __ldcg(&g_lut[b * 257 + tid]);
        }
        if (tid == 256) {
            slut[256] = NC;
            smeta[0] = __ldcg(&g_meta[2 * b]);
            smeta[1] = __ldcg(&g_meta[2 * b + 1]);
        }
        __syncthreads();

        const float lo = smeta[0], scale = smeta[1];
        float s = 0.0f;
        if (ok) {
            int q = (int)((tk - lo) * scale);
            q = min(255, max(q, 0));
            int j = slut[q], e = slut[q + 1];
            while (j < e && scs[j] <= tk) j++;     // exact lower-bound (bucket fn monotone)
            float dlo = (j >= 1) ? tk - scs[j - 1] : CUDART_INF_F;
            float dhi = (j < NC) ? scs[j] - tk     : CUDART_INF_F;
            float d = fminf(dlo, dhi);
            s = d * d;
            if (j >= 1) atomicMin(&scmin[j - 1], __float_as_uint(dlo));
            if (j < NC) atomicMin(&scmin[j],     __float_as_uint(dhi));
        }

        #pragma unroll
        for (int o = 16; o; o >>= 1) {
            s   += __shfl_xor_sync(0xFFFFFFFFu, s, o);
            mloc = fmaxf(mloc, __shfl_xor_sync(0xFFFFFFFFu, mloc, o));
        }
        if (lane == 0) { sred[wid] = s; sred2[wid] = mloc; }
        int banyinv = __syncthreads_or(inv);

        if (tid < NC) {
            unsigned sm = scmin[tid];
            if (sm != 0x7F800000u) atomicMax(&g_ckey[b * NC + tid], ~sm);
        }
        if (tid == 0) {
            float bs = sred[0], bm = sred2[0];
            #pragma unroll
            for (int j = 1; j < 32; j++) { bs += sred[j]; bm = fmaxf(bm, sred2[j]); }
            g_d2part[chunk] = bs;
            atomicMax(&g_maxkey, fkey(bm));
            if (banyinv) g_anyinv = 1;             // benign same-value race
        }
    }

    // ---------------------------- ticket ----------------------------
    __threadfence();
    if (tid == 0) is_last = (atomicAdd(&g_cnt, 1u) == NBLK - 1);
    __syncthreads();
    if (!is_last) return;
    __threadfence();

    // ================= FINALIZE: all 4 batches at once (group = tid>>8) =================
    const int x  = tid & 255;          // slot within batch
    const int bb = tid >> 8;           // batch
    const int wl = wid & 7;            // warp index within group
    const int gb = (wid >> 3) << 3;    // group's base warp

    float    c   = __ldcg(&g_csort[bb * NC + x]);
    unsigned key = __ldcg(&g_ckey[bb * NC + x]);
    g_ckey[bb * NC + x] = 0u;          // reset for next replay
    float d = key ? __uint_as_float(~key) : CUDART_INF_F;

    if (x == 255) sred[bb] = c;        // per-batch max center
    __syncthreads();
    const float mt = funkey(g_maxkey);
    const float mc = fmaxf(fmaxf(sred[0], sred[1]), fmaxf(sred[2], sred[3]));
    const float mx = fmaxf(mt, mc), mn = fminf(mt, mc);
    const float pad = mx + (mx - mn) + 1.0f;   // EPS = 1.0
    const int anyinv = g_anyinv;
    __syncthreads();                   // sred reads done before reuse below

    // prefix-min of (d - c) within the 256-thread group
    float v1 = d - c;
    #pragma unroll
    for (int o = 1; o < 32; o <<= 1) {
        float u = __shfl_up_sync(0xFFFFFFFFu, v1, o);
        if (lane >= o) v1 = fminf(v1, u);
    }
    if (lane == 31) wa[wid] = v1;
    __syncthreads();
    float pre = CUDART_INF_F;
    #pragma unroll
    for (int j = 0; j < 7; j++)
        if (j < wl) pre = fminf(pre, wa[gb + j]);
    float As = fminf(v1, pre);
    __syncthreads();

    // suffix-min of (d + c) within the group
    float v2 = d + c;
    #pragma unroll
    for (int o = 1; o < 32; o <<= 1) {
        float u = __shfl_down_sync(0xFFFFFFFFu, v2, o);
        if (lane + o < 32) v2 = fminf(v2, u);
    }
    if (lane == 0) wa[wid] = v2;
    __syncthreads();
    float suf = CUDART_INF_F;
    #pragma unroll
    for (int j = 1; j < 8; j++)
        if (j > wl) suf = fminf(suf, wa[gb + j]);
    float Bs = fminf(v2, suf);

    float Di = fminf(As + c, Bs - c);
    if (anyinv) Di = fminf(Di, pad - c);
    float acc = Di * Di;
    if (tid == 0 && !anyinv) { float dp = pad - mt; acc += dp * dp; }  // pad-center row
    if (tid < NCON) acc += g_d2part[tid];
    if (tid == 0) {
        g_cnt = 0u;
        g_flag[0] = 0u; g_flag[1] = 0u; g_flag[2] = 0u; g_flag[3] = 0u;
    }

    #pragma unroll
    for (int o = 16; o; o >>= 1) acc += __shfl_xor_sync(0xFFFFFFFFu, acc, o);
    __syncthreads();                    // protect wa/sred reuse ordering
    if (lane == 0) sred[wid] = acc;
    __syncthreads();
    if (tid == 0) {
        float tot = sred[0];
        #pragma unroll
        for (int j = 1; j < 32; j++) tot += sred[j];
        out[0] = tot * 0.25f;
    }
}

// ---------------------------------------------------------------------------
extern "C" void kernel_launch(void* const* d_in, const int* in_sizes, int n_in,
                              void* d_out, int out_size) {
    const float* target  = (const float*)d_in[0];
    const float* centers = (const float*)d_in[1];
    const int*   mask    = (const int*)d_in[2];
    float*       out     = (float*)d_out;

    k_fused<<<NBLK, 1024>>>(target, mask, centers, out);
}

// round 11
// speedup vs baseline: 1.3200x; 1.1775x over previous
#include <cuda_runtime.h>
#include <math_constants.h>

#define B       4
#define M       76800          // 240*320 targets per batch
#define NC      256
#define NBLK    300            // b = bid&3, sub = bid>>2; 2 blocks/SM, one wave

__device__ unsigned g_maxkey;          // monotonic masked-max key (idempotent across replays)
__device__ int      g_anyinv;          // any masked-out pixel (idempotent)
__device__ float    g_csort[B * NC];   // sorted centers (published by bids 0..3; read only after ticket)
__device__ unsigned g_ckey[B * NC];    // min dist per sorted slot, INVERTED key; 0 == +inf (reset by finalizer)
__device__ float    g_d2part[NBLK];
__device__ unsigned g_cnt;             // ticket (reset by finalizer)

__device__ __forceinline__ unsigned fkey(float f) {
    unsigned b = __float_as_uint(f);
    return b ^ ((b & 0x80000000u) ? 0xFFFFFFFFu : 0x80000000u);
}
__device__ __forceinline__ float funkey(unsigned k) {
    return __uint_as_float(k ^ ((k & 0x80000000u) ? 0x80000000u : 0xFFFFFFFFu));
}

__global__ void __launch_bounds__(1024, 2) k_fused(const float* __restrict__ target,
                                                   const int*   __restrict__ mask,
                                                   const float* __restrict__ centers,
                                                   float*       __restrict__ out) {
    __shared__ float    scs[NC];       // deterministically sorted centers
    __shared__ float    cval[NC];      // scatter scratch
    __shared__ int      cidx[NC];
    __shared__ int      hist[NC];
    __shared__ int      start[NC + 1];
    __shared__ unsigned scmin[NC];
    __shared__ float    wa[16];
    __shared__ int      swa[8];
    __shared__ float    sred[32], sred2[32];
    __shared__ bool     is_last;

    const int tid  = threadIdx.x;      // 0..1023
    const int bid  = blockIdx.x;
    const int lane = tid & 31;
    const int wid  = tid >> 5;
    const int b    = bid & 3;
    const int sub  = bid >> 2;

    // ---- kick off DRAM loads first (overlap with the local sort) ----
    const int gi = b * M + sub * 1024 + tid;
    const float tk = target[gi];
    const int   ok = mask[gi];

    float myc = 0.0f;
    if (tid < NC) {
        myc = centers[b * NC + tid];   // L2-hot after first blocks
        hist[tid]  = 0;
        scmin[tid] = 0x7F800000u;      // +inf
    }
    __syncthreads();

    // ---- lo/hi over centers ----
    if (tid < NC) {
        float mn = myc, mx = myc;
        #pragma unroll
        for (int o = 16; o; o >>= 1) {
            mn = fminf(mn, __shfl_xor_sync(0xFFFFFFFFu, mn, o));
            mx = fmaxf(mx, __shfl_xor_sync(0xFFFFFFFFu, mx, o));
        }
        if (lane == 0) { wa[wid] = mn; wa[8 + wid] = mx; }
    }
    __syncthreads();
    float lo = wa[0], hi = wa[8];
    #pragma unroll
    for (int j = 1; j < 8; j++) { lo = fminf(lo, wa[j]); hi = fmaxf(hi, wa[8 + j]); }
    const float scale = (hi > lo) ? 256.0f / (hi - lo) : 0.0f;

    // ---- counting sort: histogram (arrival rank) ----
    int myq = 0, myrank = 0;
    if (tid < NC) {
        myq = min(255, max(0, (int)((myc - lo) * scale)));
        myrank = atomicAdd(&hist[myq], 1);
    }
    __syncthreads();

    // exclusive prefix sum of hist -> bucket starts
    int h = 0, incl = 0;
    if (tid < NC) {
        h = hist[tid]; incl = h;
        #pragma unroll
        for (int o = 1; o < 32; o <<= 1) {
            int u = __shfl_up_sync(0xFFFFFFFFu, incl, o);
            if (lane >= o) incl += u;
        }
        if (lane == 31) swa[wid] = incl;
    }
    __syncthreads();
    if (tid < NC) {
        int add = 0;
        #pragma unroll
        for (int j = 0; j < 8; j++)
            if (j < wid) add += swa[j];
        start[tid] = add + incl - h;
    }
    if (tid == NC) start[NC] = NC;
    __syncthreads();

    // scatter (arrival order), then deterministic within-bucket re-rank
    if (tid < NC) {
        int p = start[myq] + myrank;
        cval[p] = myc; cidx[p] = tid;
    }
    __syncthreads();
    if (tid < NC) {
        const int s0 = start[myq], e0 = start[myq + 1];
        int rb = 0;
        for (int j = s0; j < e0; j++) {
            float cv = cval[j];
            if (cv < myc || (cv == myc && cidx[j] < tid)) rb++;
        }
        scs[s0 + rb] = myc;            // fully sorted, deterministic (value, orig-idx) order
    }
    __syncthreads();

    if (bid < B && tid < NC) g_csort[b * NC + tid] = scs[tid];  // for finalizer only

    // ---- main pass: exact bracket via bucket LUT + one-bucket scan ----
    float s = 0.0f;
    float mloc = ok ? tk : -CUDART_INF_F;
    const int inv = !ok;
    if (ok) {
        int qt = min(255, max(0, (int)((tk - lo) * scale)));
        int j = start[qt], e = start[qt + 1];
        while (j < e && scs[j] <= tk) j++;        // exact lower-bound count
        float dlo = (j >= 1) ? tk - scs[j - 1] : CUDART_INF_F;
        float dhi = (j < NC) ? scs[j] - tk     : CUDART_INF_F;
        float d = fminf(dlo, dhi);
        s = d * d;
        if (j >= 1) atomicMin(&scmin[j - 1], __float_as_uint(dlo));
        if (j < NC) atomicMin(&scmin[j],     __float_as_uint(dhi));
    }

    #pragma unroll
    for (int o = 16; o; o >>= 1) {
        s    += __shfl_xor_sync(0xFFFFFFFFu, s, o);
        mloc  = fmaxf(mloc, __shfl_xor_sync(0xFFFFFFFFu, mloc, o));
    }
    if (lane == 0) { sred[wid] = s; sred2[wid] = mloc; }
    int banyinv = __syncthreads_or(inv);

    if (tid < NC) {
        unsigned sm = scmin[tid];
        if (sm != 0x7F800000u) atomicMax(&g_ckey[b * NC + tid], ~sm);
    }
    if (tid == 0) {
        float bs = sred[0], bm = sred2[0];
        #pragma unroll
        for (int j = 1; j < 32; j++) { bs += sred[j]; bm = fmaxf(bm, sred2[j]); }
        g_d2part[bid] = bs;
        atomicMax(&g_maxkey, fkey(bm));
        if (banyinv) g_anyinv = 1;     // benign same-value race
    }

    // ---------------------------- ticket ----------------------------
    __threadfence();
    if (tid == 0) is_last = (atomicAdd(&g_cnt, 1u) == NBLK - 1);
    __syncthreads();
    if (!is_last) return;
    __threadfence();

    // ================= FINALIZE: all 4 batches at once (group = tid>>8) =================
    const int x  = tid & 255;          // sorted slot within batch
    const int bb = tid >> 8;           // batch
    const int wl = wid & 7;            // warp index within group
    const int gb = (wid >> 3) << 3;    // group's base warp

    float    c   = __ldcg(&g_csort[bb * NC + x]);
    unsigned key = __ldcg(&g_ckey[bb * NC + x]);
    g_ckey[bb * NC + x] = 0u;          // reset for next replay
    float d = key ? __uint_as_float(~key) : CUDART_INF_F;

    if (x == 255) sred[bb] = c;        // per-batch max center
    __syncthreads();
    const float mt = funkey(g_maxkey);
    const float mc = fmaxf(fmaxf(sred[0], sred[1]), fmaxf(sred[2], sred[3]));
    const float mx = fmaxf(mt, mc), mn = fminf(mt, mc);
    const float pad = mx + (mx - mn) + 1.0f;   // EPS = 1.0
    const int anyinv = g_anyinv;
    __syncthreads();

    // prefix-min of (d - c) within the 256-thread group
    float v1 = d - c;
    #pragma unroll
    for (int o = 1; o < 32; o <<= 1) {
        float u = __shfl_up_sync(0xFFFFFFFFu, v1, o);
        if (lane >= o) v1 = fminf(v1, u);
    }
    if (lane == 31) wa[wid & 15] = v1;       // wa has 16 slots; wid 0..31 -> need 32
    __syncthreads();
    // NOTE: 32 warps need 32 slots; reuse sred2 (32 floats) instead of wa
    if (lane == 31) sred2[wid] = v1;
    __syncthreads();
    float pre = CUDART_INF_F;
    #pragma unroll
    for (int j = 0; j < 7; j++)
        if (j < wl) pre = fminf(pre, sred2[gb + j]);
    float As = fminf(v1, pre);
    __syncthreads();

    // suffix-min of (d + c) within the group
    float v2 = d + c;
    #pragma unroll
    for (int o = 1; o < 32; o <<= 1) {
        float u = __shfl_down_sync(0xFFFFFFFFu, v2, o);
        if (lane + o < 32) v2 = fminf(v2, u);
    }
    if (lane == 0) sred2[wid] = v2;
    __syncthreads();
    float suf = CUDART_INF_F;
    #pragma unroll
    for (int j = 1; j < 8; j++)
        if (j > wl) suf = fminf(suf, sred2[gb + j]);
    float Bs = fminf(v2, suf);

    float Di = fminf(As + c, Bs - c);
    if (anyinv) Di = fminf(Di, pad - c);
    float acc = Di * Di;
    if (tid == 0 && !anyinv) { float dp = pad - mt; acc += dp * dp; }  // pad-center row
    if (tid < NBLK) acc += g_d2part[tid];
    if (tid == 0) g_cnt = 0u;          // reset ticket for next replay

    #pragma unroll
    for (int o = 16; o; o >>= 1) acc += __shfl_xor_sync(0xFFFFFFFFu, acc, o);
    __syncthreads();
    if (lane == 0) sred[wid] = acc;
    __syncthreads();
    if (tid == 0) {
        float tot = sred[0];
        #pragma unroll
        for (int j = 1; j < 32; j++) tot += sred[j];
        out[0] = tot * 0.25f;
    }
}

// ---------------------------------------------------------------------------
extern "C" void kernel_launch(void* const* d_in, const int* in_sizes, int n_in,
                              void* d_out, int out_size) {
    const float* target  = (const float*)d_in[0];
    const float* centers = (const float*)d_in[1];
    const int*   mask    = (const int*)d_in[2];
    float*       out     = (float*)d_out;

    k_fused<<<NBLK, 1024>>>(target, mask, centers, out);
}